// round 16
// baseline (speedup 1.0000x reference)
#include <cuda_runtime.h>
#include <math.h>

// Problem constants
#define BB 2
#define SS 8192
#define CC 64
#define MMG 32
#define GG (SS / MMG)          // 256 groups per batch
#define BCS (BB * CC * SS)
#define WST 64                 // weight row stride ([k][c] layout; broadcast loads)

// Scratch (device globals — allocation-free)
__device__ float g_Pf[BCS];
__device__ float g_Qf[BCS];
__device__ float g_Pe[BCS];
__device__ float g_Qe[BCS];
__device__ float g_Ef[BCS];
__device__ float g_Eg[BCS];
__device__ float g_F1[BCS];
__device__ float g_agg[BCS];

typedef unsigned long long u64;

// per-team named barrier: 256 threads of team t sync on barrier id t+1 (teams 0..3)
#define TEAM_BAR(t) asm volatile("bar.sync %0, 256;" :: "r"((t) + 1) : "memory")

// ---------------------------------------------------------------------------
// packed fp32 helpers (Blackwell f32x2) + warp reduction
// ---------------------------------------------------------------------------
__device__ __forceinline__ void ffma2(u64& d, u64 a, u64 b) {
    asm("fma.rn.f32x2 %0, %1, %2, %0;" : "+l"(d) : "l"(a), "l"(b));
}
__device__ __forceinline__ u64 splat2(float a) {
    u64 r; asm("mov.b64 %0, {%1, %1};" : "=l"(r) : "f"(a)); return r;
}
__device__ __forceinline__ u64 pack2(float x, float y) {
    u64 r; asm("mov.b64 %0, {%1, %2};" : "=l"(r) : "f"(x), "f"(y)); return r;
}
__device__ __forceinline__ float2 unpack2(u64 v) {
    float2 r; asm("mov.b64 {%0, %1}, %2;" : "=f"(r.x), "=f"(r.y) : "l"(v)); return r;
}
// two interleaved butterfly sums (sm_100 has no redux.f32)
__device__ __forceinline__ float2 warp_rsum2(float a, float b) {
#pragma unroll
    for (int o = 16; o > 0; o >>= 1) {
        a += __shfl_xor_sync(0xffffffffu, a, o);
        b += __shfl_xor_sync(0xffffffffu, b, o);
    }
    return make_float2(a, b);
}

// Packed matmul over K=64, single activation stream:
// acc[i] += Wt[k][cb+2i..] * A[k][lane]
__device__ __forceinline__ void mmT1(u64 acc[4],
                                     const float* __restrict__ sWt, int cb,
                                     const float* __restrict__ sA, int lane) {
#pragma unroll 8
    for (int k = 0; k < 64; k++) {
        ulonglong2 wlo = *reinterpret_cast<const ulonglong2*>(sWt + k * WST + cb);
        ulonglong2 whi = *reinterpret_cast<const ulonglong2*>(sWt + k * WST + cb + 4);
        u64 a = splat2(sA[k * 32 + lane]);
        ffma2(acc[0], wlo.x, a); ffma2(acc[1], wlo.y, a);
        ffma2(acc[2], whi.x, a); ffma2(acc[3], whi.y, a);
    }
}

// scalar helper used by kernel A
__device__ __forceinline__ void mm64_acc(float acc[8], const float* __restrict__ sW,
                                         int wstride, int cbase,
                                         const float* __restrict__ sA, int lane) {
#pragma unroll 4
    for (int q = 0; q < 16; q++) {
        float a0 = sA[(4 * q + 0) * 32 + lane];
        float a1 = sA[(4 * q + 1) * 32 + lane];
        float a2 = sA[(4 * q + 2) * 32 + lane];
        float a3 = sA[(4 * q + 3) * 32 + lane];
#pragma unroll
        for (int i = 0; i < 8; i++) {
            float4 w = *reinterpret_cast<const float4*>(&sW[(cbase + i) * wstride + 4 * q]);
            acc[i] = fmaf(w.x, a0, acc[i]);
            acc[i] = fmaf(w.y, a1, acc[i]);
            acc[i] = fmaf(w.z, a2, acc[i]);
            acc[i] = fmaf(w.w, a3, acc[i]);
        }
    }
}

// ---------------------------------------------------------------------------
// Kernel A: per-point linear projections — unchanged
// ---------------------------------------------------------------------------
struct SmemA {
    float Wpf[64 * 64];
    float Wqf[64 * 64];
    float Wf1[64 * 64];
    float W1x[64 * 8];
    float Wex[64 * 8];
    float W2x[64 * 8];
    float F1t[64 * 32];
    float F2t[64 * 32];
    float X1[3 * 32];
    float X2[3 * 32];
};

__global__ void kernelA(const float* __restrict__ xyz1, const float* __restrict__ feat1,
                        const float* __restrict__ xyz2, const float* __restrict__ feat2,
                        const float* __restrict__ w10, const float* __restrict__ b10,
                        const float* __restrict__ wx1, const float* __restrict__ bx1,
                        const float* __restrict__ wx2, const float* __restrict__ bx2,
                        const float* __restrict__ w30, const float* __restrict__ b30) {
    extern __shared__ float smem_raw[];
    SmemA& s = *reinterpret_cast<SmemA*>(smem_raw);
    int tid = threadIdx.x;
    int t = blockIdx.x;
    int b = t >> 8;
    int s0 = (t & 255) * 32;

    for (int idx = tid; idx < 4096; idx += 256) {
        int c = idx >> 6, j = idx & 63;
        s.Wpf[idx] = w10[c * 138 + 10 + j];
        s.Wqf[idx] = w10[c * 138 + 74 + j];
        s.Wf1[idx] = w30[c * 192 + 64 + j];
    }
    for (int idx = tid; idx < 384; idx += 256) {
        int c = idx / 6, j = idx % 6;
        s.W1x[c * 8 + j] = w10[c * 138 + j];
        s.Wex[c * 8 + j] = wx1[c * 10 + j];
        s.W2x[c * 8 + j] = wx2[c * 10 + j];
    }
    for (int idx = tid; idx < 2048; idx += 256) {
        int c = idx >> 5, k = idx & 31;
        s.F1t[idx] = feat1[b * CC * SS + c * SS + s0 + k];
        s.F2t[idx] = feat2[b * CC * SS + c * SS + s0 + k];
    }
    for (int idx = tid; idx < 96; idx += 256) {
        int i = idx >> 5, k = idx & 31;
        s.X1[idx] = xyz1[b * 3 * SS + i * SS + s0 + k];
        s.X2[idx] = xyz2[b * 3 * SS + i * SS + s0 + k];
    }
    __syncthreads();

    int lane = tid & 31;
    int cb = (tid >> 5) * 8;
    float x10 = s.X1[lane], x11 = s.X1[32 + lane], x12 = s.X1[64 + lane];
    float x20 = s.X2[lane], x21 = s.X2[32 + lane], x22 = s.X2[64 + lane];

    float accPf[8], accQf[8], accF1[8];
#pragma unroll
    for (int i = 0; i < 8; i++) {
        accPf[i] = __ldg(&b10[cb + i]);
        accQf[i] = 0.f;
        accF1[i] = __ldg(&b30[cb + i]);
    }
    mm64_acc(accPf, s.Wpf, 64, cb, s.F1t, lane);
    mm64_acc(accF1, s.Wf1, 64, cb, s.F1t, lane);
    mm64_acc(accQf, s.Wqf, 64, cb, s.F2t, lane);

#pragma unroll
    for (int i = 0; i < 8; i++) {
        int c = cb + i;
        long base = (long)b * CC * SS + (long)c * SS + s0 + lane;
        float pf = accPf[i] + s.W1x[c * 8 + 0] * x10 + s.W1x[c * 8 + 1] * x11 + s.W1x[c * 8 + 2] * x12;
        float qf = accQf[i] + s.W1x[c * 8 + 3] * x20 + s.W1x[c * 8 + 4] * x21 + s.W1x[c * 8 + 5] * x22;
        g_Pf[base] = pf;
        g_Qf[base] = qf;
        g_F1[base] = accF1[i];
        g_Pe[base] = __ldg(&bx1[c]) + s.Wex[c * 8 + 0] * x10 + s.Wex[c * 8 + 1] * x11 + s.Wex[c * 8 + 2] * x12;
        g_Qe[base] = s.Wex[c * 8 + 3] * x20 + s.Wex[c * 8 + 4] * x21 + s.Wex[c * 8 + 5] * x22;
        g_Ef[base] = __ldg(&bx2[c]) + s.W2x[c * 8 + 0] * x10 + s.W2x[c * 8 + 1] * x11 + s.W2x[c * 8 + 2] * x12;
        g_Eg[base] = s.W2x[c * 8 + 3] * x10 + s.W2x[c * 8 + 4] * x11 + s.W2x[c * 8 + 5] * x12;
    }
}

// ---------------------------------------------------------------------------
// Kernel B: stage 1 — 1024 threads, 4 teams x 8 warps, 1 s-point per team-pass
// grid = BB*GG*2; 3 team-barriers per pass; merged step4+step1(p+1)
// ---------------------------------------------------------------------------
struct SmemB {
    float W11t[64 * WST];
    float W20t[128 * WST];
    float W21t[64 * WST];
    float W1d[64 * 4];
    float Wed[64 * 4];
    float B11[64], B20[64], B21[64];
    float Pf[64 * 16], Pe[64 * 16];     // this half's 16 s-points, [c][slL]
    float X1h[3 * 16];
    float X2[3 * 32];
    float H[4][64 * 32];
    float PE[4][64 * 32];
    float PN[4][64 * 32];
    float U[4][64 * 32];
};

__global__ void __launch_bounds__(1024, 1)
kernelB(const float* __restrict__ xyz1, const float* __restrict__ xyz2,
        const float* __restrict__ w10, const float* __restrict__ wx1,
        const float* __restrict__ w11, const float* __restrict__ b11,
        const float* __restrict__ w20, const float* __restrict__ b20,
        const float* __restrict__ w21, const float* __restrict__ b21) {
    extern __shared__ float smem_raw[];
    SmemB& s = *reinterpret_cast<SmemB*>(smem_raw);
    int tid = threadIdx.x;
    int bid = blockIdx.x;
    int b = bid >> 9;
    int g = (bid >> 1) & 255;
    int half = bid & 1;
    int sb = g * MMG;
    int sbh = sb + half * 16;
    long cbase = (long)b * CC * SS;

    for (int idx = tid; idx < 4096; idx += 1024) {
        int c = idx >> 6, k = idx & 63;
        s.W11t[k * WST + c] = w11[idx];
        s.W21t[k * WST + c] = w21[idx];
    }
    for (int idx = tid; idx < 8192; idx += 1024) {
        int c = idx >> 7, k = idx & 127;
        s.W20t[k * WST + c] = w20[idx];
    }
    if (tid < 256) {
        int c = tid >> 2, j = tid & 3;
        s.W1d[tid] = w10[c * 138 + 6 + j];
        s.Wed[tid] = wx1[c * 10 + 6 + j];
    }
    if (tid >= 256 && tid < 320) {
        int c = tid - 256;
        s.B11[c] = b11[c];
        s.B20[c] = b20[c];
        s.B21[c] = b21[c];
    }
    if (tid >= 512 && tid < 1024) {
        int i = tid - 512;           // 512 threads for 1024 elems -> 2 each
#pragma unroll
        for (int r = 0; r < 2; r++) {
            int idx = i + r * 512;
            int c = idx >> 4, sl = idx & 15;
            s.Pf[c * 16 + sl] = g_Pf[cbase + (long)c * SS + sbh + sl];
            s.Pe[c * 16 + sl] = g_Pe[cbase + (long)c * SS + sbh + sl];
        }
    }
    if (tid >= 448 && tid < 496) {
        int i = tid - 448;
        int d = i >> 4, sl = i & 15;
        s.X1h[d * 16 + sl] = xyz1[b * 3 * SS + d * SS + sbh + sl];
    }
    if (tid >= 320 && tid < 416) {
        int i = tid - 320;
        int d = i >> 5, j = i & 31;
        s.X2[d * 32 + j] = xyz2[b * 3 * SS + d * SS + sb + j];
    }
    __syncthreads();

    int lane = tid & 31;
    int wid = tid >> 5;
    int team = wid >> 3;          // 0..3
    int cb = (wid & 7) * 8;
    long outbase = cbase + sb;

    float qf[8], qe[8];
#pragma unroll
    for (int i = 0; i < 8; i++) {
        long base = cbase + (long)(cb + i) * SS + sb + lane;
        qf[i] = __ldg(&g_Qf[base]);
        qe[i] = __ldg(&g_Qe[base]);
    }

    float nx0 = s.X2[lane], nx1 = s.X2[32 + lane], nx2 = s.X2[64 + lane];

    float* H = s.H[team];
    float* PE = s.PE[team];
    float* PN = s.PN[team];
    float* U = s.U[team];

    // step 1 for pass p: dynamic parts (H, PE) for s-point slL = 4p + team
    auto do_step1 = [&](int p) {
        int slL = 4 * p + team;
        float px0 = s.X1h[slL], px1 = s.X1h[16 + slL], px2 = s.X1h[32 + slL];
        float d0 = nx0 - px0, d1 = nx1 - px1, d2 = nx2 - px2;
        float euc = sqrtf(d0 * d0 + d1 * d1 + d2 * d2 + 1e-20f);
#pragma unroll
        for (int i = 0; i < 8; i++) {
            int c = cb + i;
            float w0 = s.W1d[c * 4 + 0], w1 = s.W1d[c * 4 + 1], w2 = s.W1d[c * 4 + 2], w3 = s.W1d[c * 4 + 3];
            float h = s.Pf[c * 16 + slL] + qf[i] + w0 * d0 + w1 * d1 + w2 * d2 + w3 * euc;
            H[c * 32 + lane] = fmaxf(h, 0.f);
            float v0 = s.Wed[c * 4 + 0], v1 = s.Wed[c * 4 + 1], v2 = s.Wed[c * 4 + 2], v3 = s.Wed[c * 4 + 3];
            float pe = s.Pe[c * 16 + slL] + qe[i] + v0 * d0 + v1 * d1 + v2 * d2 + v3 * euc;
            PE[c * 32 + lane] = fmaxf(pe, 0.f);
        }
    };

    do_step1(0);
    TEAM_BAR(team);

    for (int p = 0; p < 4; p++) {
        int sl = half * 16 + 4 * p + team;

        // --- step 2: pi_new = relu(W1_1 @ H + b1_1) ---
        u64 acc[4];
#pragma unroll
        for (int i = 0; i < 4; i++) acc[i] = *reinterpret_cast<const u64*>(&s.B11[cb + 2 * i]);
        mmT1(acc, s.W11t, cb, H, lane);
#pragma unroll
        for (int i = 0; i < 4; i++) {
            float2 r = unpack2(acc[i]);
            PN[(cb + 2 * i) * 32 + lane] = fmaxf(r.x, 0.f);
            PN[(cb + 2 * i + 1) * 32 + lane] = fmaxf(r.y, 0.f);
        }
        TEAM_BAR(team);

        // --- step 3: U = relu(W2_0 @ [PE; PN] + b2_0) ---
#pragma unroll
        for (int i = 0; i < 4; i++) acc[i] = *reinterpret_cast<const u64*>(&s.B20[cb + 2 * i]);
        mmT1(acc, s.W20t, cb, PE, lane);
        mmT1(acc, s.W20t + 64 * WST, cb, PN, lane);
#pragma unroll
        for (int i = 0; i < 4; i++) {
            float2 r = unpack2(acc[i]);
            U[(cb + 2 * i) * 32 + lane] = fmaxf(r.x, 0.f);
            U[(cb + 2 * i + 1) * 32 + lane] = fmaxf(r.y, 0.f);
        }
        TEAM_BAR(team);

        // --- merged phase: step 4 (reads U, PN) + step 1(p+1) (writes H', PE') ---
        // H dead since step 2's barrier; PE dead since step 3's barrier.
#pragma unroll
        for (int i = 0; i < 4; i++) acc[i] = *reinterpret_cast<const u64*>(&s.B21[cb + 2 * i]);
        mmT1(acc, s.W21t, cb, U, lane);

        if (p < 3) do_step1(p + 1);

#pragma unroll
        for (int i = 0; i < 4; i++) {
            float2 l = unpack2(acc[i]);
            int c0 = cb + 2 * i, c1 = c0 + 1;
            float pn0 = PN[c0 * 32 + lane];
            float pn1 = PN[c1 * 32 + lane];
            float e0 = __expf(fmaxf(l.x, 0.f));
            float e1 = __expf(fmaxf(l.y, 0.f));
            float2 r0 = warp_rsum2(e0, e0 * pn0);
            float2 r1 = warp_rsum2(e1, e1 * pn1);
            if (lane == 0) {
                g_agg[outbase + (long)c0 * SS + sl] = __fdividef(r0.y, r0.x);
                g_agg[outbase + (long)c1 * SS + sl] = __fdividef(r1.y, r1.x);
            }
        }
        TEAM_BAR(team);
    }
}

// ---------------------------------------------------------------------------
// Kernel C: stage 2 — 1024 threads, 4 teams x 8 warps, 1 s-point per team-pass
// grid = BB*GG*2; hoisted G; merged step3+step1(p+1); 2 barriers per pass
// ---------------------------------------------------------------------------
struct SmemC {
    float W30at[64 * WST];
    float W30bt[64 * WST];
    float W31t[64 * WST];
    float W2d[64 * 4];
    float B31[64];
    float Eg[64 * 32], PAG[64 * 32];
    float Ef_h[64 * 16], F1_h[64 * 16];
    float X1[3 * 32];
    float G[64 * 32];
    float P[4][64 * 32];
    float T[4][64 * 32];
};

__global__ void __launch_bounds__(1024, 1)
kernelC(const float* __restrict__ xyz1, const float* __restrict__ wx2,
        const float* __restrict__ w30, const float* __restrict__ w31,
        const float* __restrict__ b31, float* __restrict__ out) {
    extern __shared__ float smem_raw[];
    SmemC& s = *reinterpret_cast<SmemC*>(smem_raw);
    int tid = threadIdx.x;
    int bid = blockIdx.x;
    int b = bid >> 9;
    int g = (bid >> 1) & 255;
    int half = bid & 1;
    int sb = g * MMG;
    int sbh = sb + half * 16;
    long cbase = (long)b * CC * SS;

    for (int idx = tid; idx < 4096; idx += 1024) {
        int c = idx >> 6, k = idx & 63;
        s.W30at[k * WST + c] = w30[c * 192 + k];
        s.W30bt[k * WST + c] = w30[c * 192 + 128 + k];
        s.W31t[k * WST + c] = w31[c * 64 + k];
    }
    if (tid < 256) {
        int c = tid >> 2, j = tid & 3;
        s.W2d[tid] = wx2[c * 10 + 6 + j];
    }
    if (tid >= 256 && tid < 320) s.B31[tid - 256] = b31[tid - 256];
    for (int idx = tid; idx < 2048; idx += 1024) {
        int c = idx >> 5, k = idx & 31;
        long base = cbase + (long)c * SS + sb + k;
        s.Eg[idx] = g_Eg[base];
        s.PAG[idx] = g_agg[base];
    }
    if (tid >= 512 && tid < 1024) {
        int i = tid - 512;
#pragma unroll
        for (int r = 0; r < 2; r++) {
            int idx = i + r * 512;
            int c = idx >> 4, sl = idx & 15;
            s.Ef_h[c * 16 + sl] = g_Ef[cbase + (long)c * SS + sbh + sl];
            s.F1_h[c * 16 + sl] = g_F1[cbase + (long)c * SS + sbh + sl];
        }
    }
    if (tid >= 384 && tid < 480) {
        int i = tid - 384;
        int d = i >> 5, k = i & 31;
        s.X1[d * 32 + k] = xyz1[b * 3 * SS + d * SS + sb + k];
    }
    __syncthreads();

    int lane = tid & 31;
    int wid = tid >> 5;
    int team = wid >> 3;
    int cb = (wid & 7) * 8;
    long outbase = cbase + sb;

    // --- G = W30b @ pi_agg (s-independent): 32 warps x 2 channels ---
    {
        int c2 = wid * 2;
        u64 gacc = 0ull;
#pragma unroll 8
        for (int k = 0; k < 64; k++) {
            u64 w = *reinterpret_cast<const u64*>(s.W30bt + k * WST + c2);
            u64 a = splat2(s.PAG[k * 32 + lane]);
            ffma2(gacc, w, a);
        }
        float2 v = unpack2(gacc);
        s.G[(c2 + 0) * 32 + lane] = v.x;
        s.G[(c2 + 1) * 32 + lane] = v.y;
    }
    __syncthreads();

    float nx0 = s.X1[lane], nx1 = s.X1[32 + lane], nx2 = s.X1[64 + lane];

    float* P = s.P[team];
    float* T = s.T[team];

    auto do_step1 = [&](int p) {
        int slL = 4 * p + team;
        int sl = half * 16 + slL;
        float px0 = s.X1[sl], px1 = s.X1[32 + sl], px2 = s.X1[64 + sl];
        float d0 = nx0 - px0, d1 = nx1 - px1, d2 = nx2 - px2;
        float euc = sqrtf(d0 * d0 + d1 * d1 + d2 * d2 + 1e-20f);
#pragma unroll
        for (int i = 0; i < 8; i++) {
            int c = cb + i;
            float w0 = s.W2d[c * 4 + 0], w1 = s.W2d[c * 4 + 1], w2 = s.W2d[c * 4 + 2], w3 = s.W2d[c * 4 + 3];
            float v = s.Ef_h[c * 16 + slL] + s.Eg[c * 32 + lane]
                    + w0 * d0 + w1 * d1 + w2 * d2 + w3 * euc;
            P[c * 32 + lane] = fmaxf(v, 0.f);
        }
    };

    do_step1(0);
    TEAM_BAR(team);

    for (int p = 0; p < 4; p++) {
        int slL = 4 * p + team;
        int sl = half * 16 + slL;

        // --- step 2: T = relu(G + F1[.,sl] + W3_0a @ pc_enc) ---
        u64 acc[4];
#pragma unroll
        for (int i = 0; i < 4; i++) {
            int c0 = cb + 2 * i, c1 = c0 + 1;
            acc[i] = pack2(s.G[c0 * 32 + lane] + s.F1_h[c0 * 16 + slL],
                           s.G[c1 * 32 + lane] + s.F1_h[c1 * 16 + slL]);
        }
        mmT1(acc, s.W30at, cb, P, lane);
#pragma unroll
        for (int i = 0; i < 4; i++) {
            float2 r = unpack2(acc[i]);
            T[(cb + 2 * i) * 32 + lane] = fmaxf(r.x, 0.f);
            T[(cb + 2 * i + 1) * 32 + lane] = fmaxf(r.y, 0.f);
        }
        TEAM_BAR(team);

        // --- merged phase: step 3 (logits + masked softmax + aggregate)
        //     and step 1(p+1) (writes P, dead after step 2) ---
#pragma unroll
        for (int i = 0; i < 4; i++) acc[i] = *reinterpret_cast<const u64*>(&s.B31[cb + 2 * i]);
        mmT1(acc, s.W31t, cb, T, lane);

        if (p < 3) do_step1(p + 1);

#pragma unroll
        for (int i = 0; i < 4; i++) {
            float2 l = unpack2(acc[i]);
            int c0 = cb + 2 * i, c1 = c0 + 1;
            float pg0 = s.PAG[c0 * 32 + lane];
            float pg1 = s.PAG[c1 * 32 + lane];
            float e0 = (lane == sl) ? 0.f : __expf(fmaxf(l.x, 0.f));
            float e1 = (lane == sl) ? 0.f : __expf(fmaxf(l.y, 0.f));
            float2 r0 = warp_rsum2(e0, e0 * pg0);
            float2 r1 = warp_rsum2(e1, e1 * pg1);
            if (lane == 0) {
                out[outbase + (long)c0 * SS + sl] = __fdividef(r0.y, r0.x);
                out[outbase + (long)c1 * SS + sl] = __fdividef(r1.y, r1.x);
            }
        }
        TEAM_BAR(team);
    }
}

// ---------------------------------------------------------------------------
extern "C" void kernel_launch(void* const* d_in, const int* in_sizes, int n_in,
                              void* d_out, int out_size) {
    const float* xyz1 = (const float*)d_in[0];
    const float* feat1 = (const float*)d_in[1];
    const float* xyz2 = (const float*)d_in[2];
    const float* feat2 = (const float*)d_in[3];
    const float* w10 = (const float*)d_in[4];
    const float* b10 = (const float*)d_in[5];
    const float* w11 = (const float*)d_in[6];
    const float* b11 = (const float*)d_in[7];
    const float* wx1 = (const float*)d_in[8];
    const float* bx1 = (const float*)d_in[9];
    const float* wx2 = (const float*)d_in[10];
    const float* bx2 = (const float*)d_in[11];
    const float* w20 = (const float*)d_in[12];
    const float* b20 = (const float*)d_in[13];
    const float* w21 = (const float*)d_in[14];
    const float* b21 = (const float*)d_in[15];
    const float* w30 = (const float*)d_in[16];
    const float* b30 = (const float*)d_in[17];
    const float* w31 = (const float*)d_in[18];
    const float* b31 = (const float*)d_in[19];
    float* out = (float*)d_out;

    cudaFuncSetAttribute(kernelA, cudaFuncAttributeMaxDynamicSharedMemorySize, (int)sizeof(SmemA));
    cudaFuncSetAttribute(kernelB, cudaFuncAttributeMaxDynamicSharedMemorySize, (int)sizeof(SmemB));
    cudaFuncSetAttribute(kernelC, cudaFuncAttributeMaxDynamicSharedMemorySize, (int)sizeof(SmemC));

    kernelA<<<(BB * SS) / 32, 256, sizeof(SmemA)>>>(xyz1, feat1, xyz2, feat2,
                                                    w10, b10, wx1, bx1, wx2, bx2, w30, b30);
    kernelB<<<BB * GG * 2, 1024, sizeof(SmemB)>>>(xyz1, xyz2, w10, wx1,
                                                  w11, b11, w20, b20, w21, b21);
    kernelC<<<BB * GG * 2, 1024, sizeof(SmemC)>>>(xyz1, wx2, w30, w31, b31, out);
}